// round 6
// baseline (speedup 1.0000x reference)
#include <cuda_runtime.h>
#include <cstdint>

#define NNODE 8192
#define NEDGE 262144
#define EPLUS (NEDGE + NNODE)
#define ICH   256

__device__ float g_xl[NNODE * 256];
__device__ float g_xr[NNODE * 256];
__device__ float g_h [NNODE * 128];
__device__ float g_z [NNODE * 256];
__device__ float g_re[NNODE * 128];
__device__ float g_xd[NNODE * 128];

__device__ int g_is64;
__device__ int g_src[NEDGE];
__device__ int g_dst[NEDGE];

__device__ int g_cnt[NNODE];
__device__ int g_rowptr[NNODE + 1];
__device__ int g_cursor[NNODE];
__device__ int g_col[EPLUS];

__device__ __forceinline__ float* dev_buf(int id) {
    switch (id) {
        case 0: return g_xl;
        case 1: return g_xr;
        case 2: return g_h;
        case 3: return g_z;
        case 4: return g_re;
        case 5: return g_xd;
    }
    return nullptr;
}
__device__ __forceinline__ const float* resolve_c(const float* p, int id) {
    return p ? p : (const float*)dev_buf(id);
}
__device__ __forceinline__ float* resolve_m(float* p, int id) {
    return p ? p : dev_buf(id);
}

// --------------------------------------------------------------------------
// Edge-index dtype detection + normalization.
// If edge_index is int64 (node ids < 8192), every odd int32 slot of the
// first 2*NEDGE int32s is the zero high-word. If int32, those slots are
// random node ids. Reading the first 2*NEDGE int32s is safe in BOTH cases
// (int32 buffer has exactly 2*NEDGE int32s; int64 buffer has 4*NEDGE).
// --------------------------------------------------------------------------
__global__ void k_init_detect() {
    if (blockIdx.x == 0 && threadIdx.x == 0) g_is64 = 1;
    int i = blockIdx.x * 256 + threadIdx.x;
    if (i < NNODE) g_cnt[i] = 0;
}

__global__ void k_detect(const int* __restrict__ p) {
    int i = blockIdx.x * 256 + threadIdx.x;
    if (i < NEDGE) {
        if (p[2 * i + 1] != 0) g_is64 = 0;  // any nonzero odd slot -> int32
    }
}

__global__ void k_norm(const void* __restrict__ ei) {
    int e = blockIdx.x * 256 + threadIdx.x;
    if (e >= NEDGE) return;
    int s, d;
    if (g_is64) {
        const long long* p = (const long long*)ei;
        s = (int)p[e];
        d = (int)p[NEDGE + e];
    } else {
        const int* p = (const int*)ei;
        s = p[e];
        d = p[NEDGE + e];
    }
    g_src[e] = s;
    g_dst[e] = d;
}

__global__ void k_hist() {
    int e = blockIdx.x * 256 + threadIdx.x;
    if (e < EPLUS) {
        int d = (e < NEDGE) ? g_dst[e] : (e - NEDGE);
        if ((unsigned)d < NNODE) atomicAdd(&g_cnt[d], 1);
    }
}

__global__ void k_scan() {
    __shared__ int ss[1024];
    int t = threadIdx.x;
    int loc[8];
    int run = 0;
#pragma unroll
    for (int i = 0; i < 8; i++) {
        loc[i] = run;
        run += g_cnt[t * 8 + i];
    }
    ss[t] = run;
    __syncthreads();
    for (int o = 1; o < 1024; o <<= 1) {
        int v = (t >= o) ? ss[t - o] : 0;
        __syncthreads();
        ss[t] += v;
        __syncthreads();
    }
    int base = (t == 0) ? 0 : ss[t - 1];
#pragma unroll
    for (int i = 0; i < 8; i++) {
        int v = base + loc[i];
        g_rowptr[t * 8 + i] = v;
        g_cursor[t * 8 + i] = v;
    }
    if (t == 1023) g_rowptr[NNODE] = base + run;
}

__global__ void k_scatter() {
    int e = blockIdx.x * 256 + threadIdx.x;
    if (e < EPLUS) {
        int s, d;
        if (e < NEDGE) {
            s = g_src[e];
            d = g_dst[e];
        } else {
            s = d = e - NEDGE;
        }
        if ((unsigned)d < NNODE && (unsigned)s < NNODE) {
            int pos = atomicAdd(&g_cursor[d], 1);
            if ((unsigned)pos < EPLUS) g_col[pos] = s;
        }
    }
}

// SGEMM (NT): C[M,Nn] = A[M,K] * W[Nn,K]^T. BM=128,BN=64,BK=16, 256 thr, 8x4 tile.
// EPI: 0 plain, 1 sigmoid.
template <int EPI>
__global__ void __launch_bounds__(256)
k_gemm_nt(const float* __restrict__ Ap, int Aid,
          const float* __restrict__ Wp, int Wid,
          float* __restrict__ Cp, int Cid,
          int M, int Nn, int K) {
    const float* A = resolve_c(Ap, Aid);
    const float* W = resolve_c(Wp, Wid);
    float* C = resolve_m(Cp, Cid);

    __shared__ __align__(16) float As[16][128];
    __shared__ __align__(16) float Ws[16][64];

    const int bm = blockIdx.x * 128;
    const int bn = blockIdx.y * 64;
    const int tid = threadIdx.x;
    const int tx = tid & 15;
    const int ty = tid >> 4;

    float acc[8][4];
#pragma unroll
    for (int i = 0; i < 8; i++)
#pragma unroll
        for (int j = 0; j < 4; j++) acc[i][j] = 0.f;

    const int r = tid >> 2;
    const int kq = (tid & 3) << 2;

    for (int k0 = 0; k0 < K; k0 += 16) {
        float4 a0 = *(const float4*)&A[(size_t)(bm + r) * K + k0 + kq];
        float4 a1 = *(const float4*)&A[(size_t)(bm + r + 64) * K + k0 + kq];
        float4 w0 = *(const float4*)&W[(size_t)(bn + r) * K + k0 + kq];
        As[kq + 0][r] = a0.x; As[kq + 1][r] = a0.y;
        As[kq + 2][r] = a0.z; As[kq + 3][r] = a0.w;
        As[kq + 0][r + 64] = a1.x; As[kq + 1][r + 64] = a1.y;
        As[kq + 2][r + 64] = a1.z; As[kq + 3][r + 64] = a1.w;
        Ws[kq + 0][r] = w0.x; Ws[kq + 1][r] = w0.y;
        Ws[kq + 2][r] = w0.z; Ws[kq + 3][r] = w0.w;
        __syncthreads();
#pragma unroll
        for (int k = 0; k < 16; k++) {
            float4 ra0 = *(const float4*)&As[k][ty * 8];
            float4 ra1 = *(const float4*)&As[k][ty * 8 + 4];
            float4 rw = *(const float4*)&Ws[k][tx * 4];
            float ra[8] = {ra0.x, ra0.y, ra0.z, ra0.w, ra1.x, ra1.y, ra1.z, ra1.w};
            float rv[4] = {rw.x, rw.y, rw.z, rw.w};
#pragma unroll
            for (int i = 0; i < 8; i++)
#pragma unroll
                for (int j = 0; j < 4; j++) acc[i][j] += ra[i] * rv[j];
        }
        __syncthreads();
    }

#pragma unroll
    for (int i = 0; i < 8; i++) {
        float4 o;
        if (EPI == 1) {
            o.x = 1.f / (1.f + __expf(-acc[i][0]));
            o.y = 1.f / (1.f + __expf(-acc[i][1]));
            o.z = 1.f / (1.f + __expf(-acc[i][2]));
            o.w = 1.f / (1.f + __expf(-acc[i][3]));
        } else {
            o.x = acc[i][0]; o.y = acc[i][1]; o.z = acc[i][2]; o.w = acc[i][3];
        }
        *(float4*)&C[(size_t)(bm + ty * 8 + i) * Nn + bn + tx * 4] = o;
    }
}

template <int OC>
__global__ void __launch_bounds__(256)
k_gat_agg(const float* __restrict__ att, const float* __restrict__ bias,
          float* __restrict__ outp, int outid) {
    constexpr int R = OC / 128;
    const float* xl = g_xl;
    const float* xr = g_xr;
    float* out = resolve_m(outp, outid);

    int w = (blockIdx.x * blockDim.x + threadIdx.x) >> 5;
    int lane = threadIdx.x & 31;
    if (w >= NNODE) return;

    float4 xri[R], av[R], acc[R];
#pragma unroll
    for (int t = 0; t < R; t++) {
        xri[t] = *(const float4*)&xr[(size_t)w * OC + t * 128 + lane * 4];
        av[t] = *(const float4*)&att[t * 128 + lane * 4];
        acc[t] = make_float4(0.f, 0.f, 0.f, 0.f);
    }

    float m = -1e30f, s = 0.f;
    int beg = g_rowptr[w], end = g_rowptr[w + 1];
    for (int j = beg; j < end; j++) {
        int sn = g_col[j];
        float4 xlj[R];
#pragma unroll
        for (int t = 0; t < R; t++)
            xlj[t] = *(const float4*)&xl[(size_t)sn * OC + t * 128 + lane * 4];
        float p = 0.f;
#pragma unroll
        for (int t = 0; t < R; t++) {
            float v;
            v = xlj[t].x + xri[t].x; p += av[t].x * fmaxf(v, 0.2f * v);
            v = xlj[t].y + xri[t].y; p += av[t].y * fmaxf(v, 0.2f * v);
            v = xlj[t].z + xri[t].z; p += av[t].z * fmaxf(v, 0.2f * v);
            v = xlj[t].w + xri[t].w; p += av[t].w * fmaxf(v, 0.2f * v);
        }
#pragma unroll
        for (int o = 16; o > 0; o >>= 1)
            p += __shfl_xor_sync(0xffffffffu, p, o);

        float mn = fmaxf(m, p);
        float corr = __expf(m - mn);
        float wgt = __expf(p - mn);
        s = s * corr + wgt;
#pragma unroll
        for (int t = 0; t < R; t++) {
            acc[t].x = acc[t].x * corr + wgt * xlj[t].x;
            acc[t].y = acc[t].y * corr + wgt * xlj[t].y;
            acc[t].z = acc[t].z * corr + wgt * xlj[t].z;
            acc[t].w = acc[t].w * corr + wgt * xlj[t].w;
        }
        m = mn;
    }

    float inv = 1.f / s;
#pragma unroll
    for (int t = 0; t < R; t++) {
        float4 b = *(const float4*)&bias[t * 128 + lane * 4];
        float4 o;
        o.x = fmaxf(acc[t].x * inv + b.x, 0.f);
        o.y = fmaxf(acc[t].y * inv + b.y, 0.f);
        o.z = fmaxf(acc[t].z * inv + b.z, 0.f);
        o.w = fmaxf(acc[t].w * inv + b.w, 0.f);
        *(float4*)&out[(size_t)w * OC + t * 128 + lane * 4] = o;
    }
}

__global__ void k_copy_z(float* __restrict__ dst) {
    int i = blockIdx.x * 256 + threadIdx.x;
    int n = NNODE * 256 / 4;
    if (i < n) ((float4*)dst)[i] = ((const float4*)g_z)[i];
}

extern "C" void kernel_launch(void* const* d_in, const int* in_sizes, int n_in,
                              void* d_out, int out_size) {
    const float* x = (const float*)d_in[0];
    const void* ei = d_in[1];
    const float *wl[5], *wr[5], *aa[5], *bb[5];
    for (int i = 0; i < 5; i++) {
        wl[i] = (const float*)d_in[2 + 4 * i];
        wr[i] = (const float*)d_in[3 + 4 * i];
        aa[i] = (const float*)d_in[4 + 4 * i];
        bb[i] = (const float*)d_in[5 + 4 * i];
    }
    float* out = (float*)d_out;
    float* recon = out;
    float* xrec = out + (size_t)NNODE * NNODE;
    float* zout = xrec + (size_t)NNODE * ICH;

    // CSR build with edge-index dtype detection
    k_init_detect<<<NNODE / 256, 256>>>();
    k_detect<<<(NEDGE + 255) / 256, 256>>>((const int*)ei);
    k_norm<<<(NEDGE + 255) / 256, 256>>>(ei);
    k_hist<<<(EPLUS + 255) / 256, 256>>>();
    k_scan<<<1, 1024>>>();
    k_scatter<<<(EPLUS + 255) / 256, 256>>>();

    // buffer ids: 0 g_xl, 1 g_xr, 2 g_h, 3 g_z, 4 g_re, 5 g_xd
    auto layer = [&](const float* inp, int inid, int IC, int OC, int li,
                     float* op, int oid) {
        dim3 gg(NNODE / 128, OC / 64);
        k_gemm_nt<0><<<gg, 256>>>(inp, inid, wl[li], -1, nullptr, 0, NNODE, OC, IC);
        k_gemm_nt<0><<<gg, 256>>>(inp, inid, wr[li], -1, nullptr, 1, NNODE, OC, IC);
        if (OC == 128)
            k_gat_agg<128><<<NNODE / 8, 256>>>(aa[li], bb[li], op, oid);
        else
            k_gat_agg<256><<<NNODE / 8, 256>>>(aa[li], bb[li], op, oid);
    };

    layer(x, -1, 256, 128, 0, nullptr, 2);        // L1: x -> h
    layer(nullptr, 2, 128, 256, 1, nullptr, 3);   // L2: h -> z
    layer(nullptr, 3, 256, 128, 2, nullptr, 4);   // L3: z -> re
    // recon = sigmoid(re @ re^T)
    k_gemm_nt<1><<<dim3(NNODE / 128, NNODE / 64), 256>>>(
        nullptr, 4, nullptr, 4, recon, -1, NNODE, NNODE, 128);
    layer(nullptr, 3, 256, 128, 3, nullptr, 5);   // L4: z -> xd
    layer(nullptr, 5, 128, 256, 4, xrec, -1);     // L5: xd -> x_rec
    k_copy_z<<<(NNODE * 256 / 4 + 255) / 256, 256>>>(zout);
    (void)in_sizes; (void)n_in; (void)out_size;
}

// round 8
// speedup vs baseline: 1.5370x; 1.5370x over previous
#include <cuda_runtime.h>
#include <cstdint>

#define NNODE 8192
#define NEDGE 262144
#define EPLUS (NEDGE + NNODE)
#define ICH   256

__device__ float g_xl[NNODE * 256];
__device__ float g_xr[NNODE * 256];
__device__ float g_h [NNODE * 128];
__device__ float g_z [NNODE * 256];
__device__ float g_re[NNODE * 128];
__device__ float g_xd[NNODE * 128];

__device__ int g_is64;
__device__ int g_src[NEDGE];
__device__ int g_dst[NEDGE];

__device__ int g_cnt[NNODE];
__device__ int g_rowptr[NNODE + 1];
__device__ int g_cursor[NNODE];
__device__ int g_col[EPLUS];

__device__ __forceinline__ float* dev_buf(int id) {
    switch (id) {
        case 0: return g_xl;
        case 1: return g_xr;
        case 2: return g_h;
        case 3: return g_z;
        case 4: return g_re;
        case 5: return g_xd;
    }
    return nullptr;
}
__device__ __forceinline__ const float* resolve_c(const float* p, int id) {
    return p ? p : (const float*)dev_buf(id);
}
__device__ __forceinline__ float* resolve_m(float* p, int id) {
    return p ? p : dev_buf(id);
}

// --------------------------------------------------------------------------
// CSR build with edge-index dtype detection (int64 vs int32 on device).
// --------------------------------------------------------------------------
__global__ void k_init_detect() {
    if (blockIdx.x == 0 && threadIdx.x == 0) g_is64 = 1;
    int i = blockIdx.x * 256 + threadIdx.x;
    if (i < NNODE) g_cnt[i] = 0;
}

__global__ void k_detect(const int* __restrict__ p) {
    int i = blockIdx.x * 256 + threadIdx.x;
    if (i < NEDGE) {
        if (p[2 * i + 1] != 0) g_is64 = 0;
    }
}

__global__ void k_norm(const void* __restrict__ ei) {
    int e = blockIdx.x * 256 + threadIdx.x;
    if (e >= NEDGE) return;
    int s, d;
    if (g_is64) {
        const long long* p = (const long long*)ei;
        s = (int)p[e];
        d = (int)p[NEDGE + e];
    } else {
        const int* p = (const int*)ei;
        s = p[e];
        d = p[NEDGE + e];
    }
    g_src[e] = s;
    g_dst[e] = d;
}

__global__ void k_hist() {
    int e = blockIdx.x * 256 + threadIdx.x;
    if (e < EPLUS) {
        int d = (e < NEDGE) ? g_dst[e] : (e - NEDGE);
        if ((unsigned)d < NNODE) atomicAdd(&g_cnt[d], 1);
    }
}

__global__ void k_scan() {
    __shared__ int ss[1024];
    int t = threadIdx.x;
    int loc[8];
    int run = 0;
#pragma unroll
    for (int i = 0; i < 8; i++) {
        loc[i] = run;
        run += g_cnt[t * 8 + i];
    }
    ss[t] = run;
    __syncthreads();
    for (int o = 1; o < 1024; o <<= 1) {
        int v = (t >= o) ? ss[t - o] : 0;
        __syncthreads();
        ss[t] += v;
        __syncthreads();
    }
    int base = (t == 0) ? 0 : ss[t - 1];
#pragma unroll
    for (int i = 0; i < 8; i++) {
        int v = base + loc[i];
        g_rowptr[t * 8 + i] = v;
        g_cursor[t * 8 + i] = v;
    }
    if (t == 1023) g_rowptr[NNODE] = base + run;
}

__global__ void k_scatter() {
    int e = blockIdx.x * 256 + threadIdx.x;
    if (e < EPLUS) {
        int s, d;
        if (e < NEDGE) {
            s = g_src[e];
            d = g_dst[e];
        } else {
            s = d = e - NEDGE;
        }
        if ((unsigned)d < NNODE && (unsigned)s < NNODE) {
            int pos = atomicAdd(&g_cursor[d], 1);
            if ((unsigned)pos < EPLUS) g_col[pos] = s;
        }
    }
}

// --------------------------------------------------------------------------
// fp32 SGEMM (NT) for feature transforms (proven path, unchanged).
// --------------------------------------------------------------------------
__global__ void __launch_bounds__(256)
k_gemm_nt(const float* __restrict__ Ap, int Aid,
          const float* __restrict__ Wp, int Wid,
          float* __restrict__ Cp, int Cid,
          int M, int Nn, int K) {
    const float* A = resolve_c(Ap, Aid);
    const float* W = resolve_c(Wp, Wid);
    float* C = resolve_m(Cp, Cid);

    __shared__ __align__(16) float As[16][128];
    __shared__ __align__(16) float Ws[16][64];

    const int bm = blockIdx.x * 128;
    const int bn = blockIdx.y * 64;
    const int tid = threadIdx.x;
    const int tx = tid & 15;
    const int ty = tid >> 4;

    float acc[8][4];
#pragma unroll
    for (int i = 0; i < 8; i++)
#pragma unroll
        for (int j = 0; j < 4; j++) acc[i][j] = 0.f;

    const int r = tid >> 2;
    const int kq = (tid & 3) << 2;

    for (int k0 = 0; k0 < K; k0 += 16) {
        float4 a0 = *(const float4*)&A[(size_t)(bm + r) * K + k0 + kq];
        float4 a1 = *(const float4*)&A[(size_t)(bm + r + 64) * K + k0 + kq];
        float4 w0 = *(const float4*)&W[(size_t)(bn + r) * K + k0 + kq];
        As[kq + 0][r] = a0.x; As[kq + 1][r] = a0.y;
        As[kq + 2][r] = a0.z; As[kq + 3][r] = a0.w;
        As[kq + 0][r + 64] = a1.x; As[kq + 1][r + 64] = a1.y;
        As[kq + 2][r + 64] = a1.z; As[kq + 3][r + 64] = a1.w;
        Ws[kq + 0][r] = w0.x; Ws[kq + 1][r] = w0.y;
        Ws[kq + 2][r] = w0.z; Ws[kq + 3][r] = w0.w;
        __syncthreads();
#pragma unroll
        for (int k = 0; k < 16; k++) {
            float4 ra0 = *(const float4*)&As[k][ty * 8];
            float4 ra1 = *(const float4*)&As[k][ty * 8 + 4];
            float4 rw = *(const float4*)&Ws[k][tx * 4];
            float ra[8] = {ra0.x, ra0.y, ra0.z, ra0.w, ra1.x, ra1.y, ra1.z, ra1.w};
            float rv[4] = {rw.x, rw.y, rw.z, rw.w};
#pragma unroll
            for (int i = 0; i < 8; i++)
#pragma unroll
                for (int j = 0; j < 4; j++) acc[i][j] += ra[i] * rv[j];
        }
        __syncthreads();
    }

#pragma unroll
    for (int i = 0; i < 8; i++) {
        float4 o;
        o.x = acc[i][0]; o.y = acc[i][1]; o.z = acc[i][2]; o.w = acc[i][3];
        *(float4*)&C[(size_t)(bm + ty * 8 + i) * Nn + bn + tx * 4] = o;
    }
}

// --------------------------------------------------------------------------
// Recon: sigmoid(re @ re^T), symmetric, tf32 tensor cores.
// Block tile 128x128, only upper-triangular blocks (bx >= by); mirror via
// smem transpose. 256 threads = 8 warps (4 m x 2 n), warp tile 32x64,
// mma.sync.m16n8k8 tf32 with fp32 accumulate.
// --------------------------------------------------------------------------
__device__ __forceinline__ unsigned f2tf(float f) {
    unsigned u;
    asm("cvt.rna.tf32.f32 %0, %1;" : "=r"(u) : "f"(f));
    return u;
}

__device__ __forceinline__ void mma_tf32(float* d, const unsigned* a, const unsigned* b) {
    asm volatile(
        "mma.sync.aligned.m16n8k8.row.col.f32.tf32.tf32.f32 "
        "{%0,%1,%2,%3}, {%4,%5,%6,%7}, {%8,%9}, {%0,%1,%2,%3};\n"
        : "+f"(d[0]), "+f"(d[1]), "+f"(d[2]), "+f"(d[3])
        : "r"(a[0]), "r"(a[1]), "r"(a[2]), "r"(a[3]), "r"(b[0]), "r"(b[1]));
}

#define RC_PAD 132

__global__ void __launch_bounds__(256)
k_recon_tc(float* __restrict__ C) {
    const int bxb = blockIdx.x;  // n-block
    const int byb = blockIdx.y;  // m-block
    if (byb > bxb) return;
    const int bm = byb * 128;
    const int bn = bxb * 128;

    extern __shared__ __align__(16) unsigned sm[];
    unsigned* As = sm;                  // [128][RC_PAD]
    unsigned* Bs = sm + 128 * RC_PAD;   // [128][RC_PAD]

    const int tid = threadIdx.x;

    // Stage both 128x128 tf32 tiles (K = 128 entirely resident).
#pragma unroll
    for (int i = 0; i < 32; i++) {
        int idx = tid + i * 256;                 // 8192 float4 total
        int tile = idx >> 12;
        int rem = idx & 4095;
        int row = rem >> 5;
        int c4 = (rem & 31) * 4;
        int base = tile ? bn : bm;
        float4 v = *(const float4*)&g_re[(size_t)(base + row) * 128 + c4];
        unsigned* dst = (tile ? Bs : As) + row * RC_PAD + c4;
        dst[0] = f2tf(v.x); dst[1] = f2tf(v.y);
        dst[2] = f2tf(v.z); dst[3] = f2tf(v.w);
    }
    __syncthreads();

    const int wid = tid >> 5, lane = tid & 31;
    const int wm = wid >> 1, wn = wid & 1;
    const int r = lane >> 2, c = lane & 3;

    float acc[2][8][4];
#pragma unroll
    for (int mi = 0; mi < 2; mi++)
#pragma unroll
        for (int ni = 0; ni < 8; ni++)
#pragma unroll
            for (int j = 0; j < 4; j++) acc[mi][ni][j] = 0.f;

#pragma unroll
    for (int kk = 0; kk < 16; kk++) {
        const int k0 = kk * 8;
        unsigned a[2][4], b[8][2];
#pragma unroll
        for (int mi = 0; mi < 2; mi++) {
            int mb = wm * 32 + mi * 16;
            a[mi][0] = As[(mb + r) * RC_PAD + k0 + c];
            a[mi][1] = As[(mb + r + 8) * RC_PAD + k0 + c];
            a[mi][2] = As[(mb + r) * RC_PAD + k0 + c + 4];
            a[mi][3] = As[(mb + r + 8) * RC_PAD + k0 + c + 4];
        }
#pragma unroll
        for (int ni = 0; ni < 8; ni++) {
            int nb = wn * 64 + ni * 8 + r;
            b[ni][0] = Bs[nb * RC_PAD + k0 + c];
            b[ni][1] = Bs[nb * RC_PAD + k0 + c + 4];
        }
#pragma unroll
        for (int mi = 0; mi < 2; mi++)
#pragma unroll
            for (int ni = 0; ni < 8; ni++)
                mma_tf32(acc[mi][ni], a[mi], b[ni]);
    }

    __syncthreads();  // done reading tiles; reuse smem for transpose
    float* Ct = (float*)sm;  // [n 128][m RC_PAD]
    const bool diag = (bxb == byb);

#pragma unroll
    for (int mi = 0; mi < 2; mi++) {
#pragma unroll
        for (int ni = 0; ni < 8; ni++) {
            int row0 = wm * 32 + mi * 16 + r;
            int col0 = wn * 64 + ni * 8 + 2 * c;
            float s0 = 1.f / (1.f + __expf(-acc[mi][ni][0]));
            float s1 = 1.f / (1.f + __expf(-acc[mi][ni][1]));
            float s2 = 1.f / (1.f + __expf(-acc[mi][ni][2]));
            float s3 = 1.f / (1.f + __expf(-acc[mi][ni][3]));
            float2 p01 = make_float2(s0, s1);
            float2 p23 = make_float2(s2, s3);
            *(float2*)&C[(size_t)(bm + row0) * NNODE + bn + col0] = p01;
            *(float2*)&C[(size_t)(bm + row0 + 8) * NNODE + bn + col0] = p23;
            if (!diag) {
                Ct[col0 * RC_PAD + row0] = s0;
                Ct[(col0 + 1) * RC_PAD + row0] = s1;
                Ct[col0 * RC_PAD + row0 + 8] = s2;
                Ct[(col0 + 1) * RC_PAD + row0 + 8] = s3;
            }
        }
    }

    if (!diag) {
        __syncthreads();
#pragma unroll
        for (int i = 0; i < 16; i++) {
            int idx = tid + i * 256;      // 128 n-rows x 32 float4 = 4096
            int n = idx >> 5;
            int m4 = (idx & 31) * 4;
            const float* s = &Ct[n * RC_PAD + m4];
            float4 v = make_float4(s[0], s[1], s[2], s[3]);
            *(float4*)&C[(size_t)(bn + n) * NNODE + bm + m4] = v;
        }
    }
}

// --------------------------------------------------------------------------
// GATv2 aggregation (unchanged).
// --------------------------------------------------------------------------
template <int OC>
__global__ void __launch_bounds__(256)
k_gat_agg(const float* __restrict__ att, const float* __restrict__ bias,
          float* __restrict__ outp, int outid) {
    constexpr int R = OC / 128;
    const float* xl = g_xl;
    const float* xr = g_xr;
    float* out = resolve_m(outp, outid);

    int w = (blockIdx.x * blockDim.x + threadIdx.x) >> 5;
    int lane = threadIdx.x & 31;
    if (w >= NNODE) return;

    float4 xri[R], av[R], acc[R];
#pragma unroll
    for (int t = 0; t < R; t++) {
        xri[t] = *(const float4*)&xr[(size_t)w * OC + t * 128 + lane * 4];
        av[t] = *(const float4*)&att[t * 128 + lane * 4];
        acc[t] = make_float4(0.f, 0.f, 0.f, 0.f);
    }

    float m = -1e30f, s = 0.f;
    int beg = g_rowptr[w], end = g_rowptr[w + 1];
    for (int j = beg; j < end; j++) {
        int sn = g_col[j];
        float4 xlj[R];
#pragma unroll
        for (int t = 0; t < R; t++)
            xlj[t] = *(const float4*)&xl[(size_t)sn * OC + t * 128 + lane * 4];
        float p = 0.f;
#pragma unroll
        for (int t = 0; t < R; t++) {
            float v;
            v = xlj[t].x + xri[t].x; p += av[t].x * fmaxf(v, 0.2f * v);
            v = xlj[t].y + xri[t].y; p += av[t].y * fmaxf(v, 0.2f * v);
            v = xlj[t].z + xri[t].z; p += av[t].z * fmaxf(v, 0.2f * v);
            v = xlj[t].w + xri[t].w; p += av[t].w * fmaxf(v, 0.2f * v);
        }
#pragma unroll
        for (int o = 16; o > 0; o >>= 1)
            p += __shfl_xor_sync(0xffffffffu, p, o);

        float mn = fmaxf(m, p);
        float corr = __expf(m - mn);
        float wgt = __expf(p - mn);
        s = s * corr + wgt;
#pragma unroll
        for (int t = 0; t < R; t++) {
            acc[t].x = acc[t].x * corr + wgt * xlj[t].x;
            acc[t].y = acc[t].y * corr + wgt * xlj[t].y;
            acc[t].z = acc[t].z * corr + wgt * xlj[t].z;
            acc[t].w = acc[t].w * corr + wgt * xlj[t].w;
        }
        m = mn;
    }

    float inv = 1.f / s;
#pragma unroll
    for (int t = 0; t < R; t++) {
        float4 b = *(const float4*)&bias[t * 128 + lane * 4];
        float4 o;
        o.x = fmaxf(acc[t].x * inv + b.x, 0.f);
        o.y = fmaxf(acc[t].y * inv + b.y, 0.f);
        o.z = fmaxf(acc[t].z * inv + b.z, 0.f);
        o.w = fmaxf(acc[t].w * inv + b.w, 0.f);
        *(float4*)&out[(size_t)w * OC + t * 128 + lane * 4] = o;
    }
}

__global__ void k_copy_z(float* __restrict__ dst) {
    int i = blockIdx.x * 256 + threadIdx.x;
    int n = NNODE * 256 / 4;
    if (i < n) ((float4*)dst)[i] = ((const float4*)g_z)[i];
}

extern "C" void kernel_launch(void* const* d_in, const int* in_sizes, int n_in,
                              void* d_out, int out_size) {
    const float* x = (const float*)d_in[0];
    const void* ei = d_in[1];
    const float *wl[5], *wr[5], *aa[5], *bb[5];
    for (int i = 0; i < 5; i++) {
        wl[i] = (const float*)d_in[2 + 4 * i];
        wr[i] = (const float*)d_in[3 + 4 * i];
        aa[i] = (const float*)d_in[4 + 4 * i];
        bb[i] = (const float*)d_in[5 + 4 * i];
    }
    float* out = (float*)d_out;
    float* recon = out;
    float* xrec = out + (size_t)NNODE * NNODE;
    float* zout = xrec + (size_t)NNODE * ICH;

    // CSR build with edge-index dtype detection
    k_init_detect<<<NNODE / 256, 256>>>();
    k_detect<<<(NEDGE + 255) / 256, 256>>>((const int*)ei);
    k_norm<<<(NEDGE + 255) / 256, 256>>>(ei);
    k_hist<<<(EPLUS + 255) / 256, 256>>>();
    k_scan<<<1, 1024>>>();
    k_scatter<<<(EPLUS + 255) / 256, 256>>>();

    // buffer ids: 0 g_xl, 1 g_xr, 2 g_h, 3 g_z, 4 g_re, 5 g_xd
    auto layer = [&](const float* inp, int inid, int IC, int OC, int li,
                     float* op, int oid) {
        dim3 gg(NNODE / 128, OC / 64);
        k_gemm_nt<<<gg, 256>>>(inp, inid, wl[li], -1, nullptr, 0, NNODE, OC, IC);
        k_gemm_nt<<<gg, 256>>>(inp, inid, wr[li], -1, nullptr, 1, NNODE, OC, IC);
        if (OC == 128)
            k_gat_agg<128><<<NNODE / 8, 256>>>(aa[li], bb[li], op, oid);
        else
            k_gat_agg<256><<<NNODE / 8, 256>>>(aa[li], bb[li], op, oid);
    };

    layer(x, -1, 256, 128, 0, nullptr, 2);        // L1: x -> h
    layer(nullptr, 2, 128, 256, 1, nullptr, 3);   // L2: h -> z
    layer(nullptr, 3, 256, 128, 2, nullptr, 4);   // L3: z -> re

    // recon = sigmoid(re @ re^T) — tf32 tensor cores, symmetric
    static const int RC_SMEM = 2 * 128 * RC_PAD * 4;  // 135168 B
    cudaFuncSetAttribute(k_recon_tc,
                         cudaFuncAttributeMaxDynamicSharedMemorySize, RC_SMEM);
    k_recon_tc<<<dim3(64, 64), 256, RC_SMEM>>>(recon);

    layer(nullptr, 3, 256, 128, 3, nullptr, 5);   // L4: z -> xd
    layer(nullptr, 5, 128, 256, 4, xrec, -1);     // L5: xd -> x_rec
    k_copy_z<<<(NNODE * 256 / 4 + 255) / 256, 256>>>(zout);
    (void)in_sizes; (void)n_in; (void)out_size;
}